// round 3
// baseline (speedup 1.0000x reference)
#include <cuda_runtime.h>
#include <math.h>

// Problem constants
#define H     200
#define G4    800          // 4*H
#define W     48
#define S     2047
#define MID   1023
#define BSENT 16           // sentences per block in word LSTM
#define NCTX  128          // ceil(2047/16)
#define CH_T  1024         // steps per sentence-level chain (MID+1)

// sentence-level partitioning
#define SPARTS 20          // partition blocks per (chain, layer)
#define SROWS  40          // gate rows per partition block (800/20)
#define SUNITS 10          // hidden units per partition block (200/20)
#define SPITCH 416         // floats per weight row (400 + pad); 416/4=104 float4, 104%8=4 -> conflict-free
#define GTP    801         // gate buffer pitch in word kernel (odd -> conflict-free)

// ---------------- device scratch (no cudaMalloc allowed) ----------------
__device__ float g_WT[4][H * G4];          // [ctx_ih, ctx_hh, tgt_ih, tgt_hh] transposed [k][j]
__device__ float g_bias[2][G4];            // combined bih+bhh for ctx, tgt
__device__ float g_sent_emb[S * H];        // ctx embeddings
__device__ float g_tgt_emb[H];             // target-sentence embedding
__device__ float g_h0hist[2 * CH_T * H];   // [chain][t][H] layer-0 hidden history
__device__ float g_h1hist[2 * CH_T * H];   // [chain][t][H] layer-1 hidden history
__device__ int   g_flag[2][2][SPARTS];     // [chain][layer][part] last completed step + 1

__device__ __forceinline__ float sigm(float x) { return 1.f / (1.f + expf(-x)); }

// packed fp32x2 helpers (Blackwell)
__device__ __forceinline__ void ffma2(unsigned long long& d, unsigned long long a, unsigned long long b) {
    asm("fma.rn.f32x2 %0, %1, %2, %0;" : "+l"(d) : "l"(a), "l"(b));
}
__device__ __forceinline__ unsigned long long packdup(float w) {
    unsigned long long r; asm("mov.b64 %0, {%1, %1};" : "=l"(r) : "f"(w)); return r;
}
__device__ __forceinline__ float2 unpack2(unsigned long long v) {
    float2 r; asm("mov.b64 {%0, %1}, %2;" : "=f"(r.x), "=f"(r.y) : "l"(v)); return r;
}

// ---------------- kernel 0: zero the sync flags (every replay) ----------------
__global__ void zero_cnt_kernel() {
    int i = blockIdx.x * blockDim.x + threadIdx.x;
    if (i < 2 * 2 * SPARTS) ((int*)g_flag)[i] = 0;
}

// ---------------- kernel 1: transpose word-level weights + combine biases -------
__global__ void prep_kernel(const float* ci, const float* ch,
                            const float* ti, const float* th,
                            const float* cbi, const float* cbh,
                            const float* tbi, const float* tbh) {
    int idx = blockIdx.x * blockDim.x + threadIdx.x;
    if (idx < 4 * H * G4) {
        int m = idx / (H * G4);
        int r = idx % (H * G4);
        int k = r / G4;
        int j = r % G4;
        const float* src = (m == 0) ? ci : (m == 1) ? ch : (m == 2) ? ti : th;
        g_WT[m][r] = src[j * H + k];
    }
    if (idx < 2 * G4) {
        int m = idx / G4, j = idx % G4;
        g_bias[m][j] = m ? (tbi[j] + tbh[j]) : (cbi[j] + cbh[j]);
    }
}

// ---------------- kernel 2: word-level LSTMs (ctx batched + tgt) -----------------
// blocks 0..127: 16 ctx sentences each. block 128: target sentence (tgt weights).
// 800 threads: thread tid owns gate row j=tid. x/h pair-interleaved [k][16] for f32x2.
__global__ __launch_bounds__(G4, 1) void word_lstm_kernel(const float* __restrict__ sents) {
    extern __shared__ float sm[];
    float* xs2 = sm;                     // [200][16]  x, sentence-interleaved
    float* hs2 = xs2 + H * BSENT;        // [200][16]  h
    float* cs  = hs2 + H * BSENT;        // [200][16]  c (same layout)
    float* gt  = cs + H * BSENT;         // [16][GTP]  gates

    const int  bx     = blockIdx.x;
    const bool is_tgt = (bx == NCTX);
    const int  s0     = is_tgt ? MID : bx * BSENT;
    const int  nb     = is_tgt ? 1 : ((S - s0) < BSENT ? (S - s0) : BSENT);

    const float* __restrict__ WTih = is_tgt ? g_WT[2] : g_WT[0];
    const float* __restrict__ WThh = is_tgt ? g_WT[3] : g_WT[1];
    const float* __restrict__ bias = is_tgt ? g_bias[1] : g_bias[0];

    const int tid = threadIdx.x;          // == gate row j
    for (int i = tid; i < H * BSENT; i += G4) { xs2[i] = 0.f; hs2[i] = 0.f; cs[i] = 0.f; }
    const float bj = bias[tid];
    const float* wi = WTih + tid;
    const float* wh = WThh + tid;
    __syncthreads();

    for (int t = 0; t < W; t++) {
        // stage x_t, interleaved: xs2[k*16 + b]
        for (int i = tid; i < H * BSENT; i += G4) {
            int k = i >> 4, b = i & 15;
            if (b < nb) xs2[i] = sents[(long)(s0 + b) * (W * H) + t * H + k];
        }
        __syncthreads();

        unsigned long long acc[8];
        #pragma unroll
        for (int p = 0; p < 8; p++) acc[p] = 0ull;

        // gates += Wih^T * x
        #pragma unroll 2
        for (int k = 0; k < H; k++) {
            unsigned long long w2 = packdup(wi[k * G4]);
            const ulonglong2* xr = (const ulonglong2*)(xs2 + k * BSENT);
            ulonglong2 p0 = xr[0], p1 = xr[1], p2 = xr[2], p3 = xr[3];
            ffma2(acc[0], w2, p0.x); ffma2(acc[1], w2, p0.y);
            ffma2(acc[2], w2, p1.x); ffma2(acc[3], w2, p1.y);
            ffma2(acc[4], w2, p2.x); ffma2(acc[5], w2, p2.y);
            ffma2(acc[6], w2, p3.x); ffma2(acc[7], w2, p3.y);
        }
        // gates += Whh^T * h
        #pragma unroll 2
        for (int k = 0; k < H; k++) {
            unsigned long long w2 = packdup(wh[k * G4]);
            const ulonglong2* hr = (const ulonglong2*)(hs2 + k * BSENT);
            ulonglong2 p0 = hr[0], p1 = hr[1], p2 = hr[2], p3 = hr[3];
            ffma2(acc[0], w2, p0.x); ffma2(acc[1], w2, p0.y);
            ffma2(acc[2], w2, p1.x); ffma2(acc[3], w2, p1.y);
            ffma2(acc[4], w2, p2.x); ffma2(acc[5], w2, p2.y);
            ffma2(acc[6], w2, p3.x); ffma2(acc[7], w2, p3.y);
        }
        #pragma unroll
        for (int p = 0; p < 8; p++) {
            float2 v = unpack2(acc[p]);
            gt[(2 * p) * GTP + tid]     = v.x + bj;
            gt[(2 * p + 1) * GTP + tid] = v.y + bj;
        }
        __syncthreads();

        // elementwise cell update
        for (int i = tid; i < H * BSENT; i += G4) {
            int u = i >> 4, b = i & 15;
            if (b < nb) {
                float ig = sigm(gt[b * GTP + u]);
                float fg = sigm(gt[b * GTP + H + u]);
                float gg = tanhf(gt[b * GTP + 2 * H + u]);
                float og = sigm(gt[b * GTP + 3 * H + u]);
                float c  = fg * cs[i] + ig * gg;
                cs[i] = c;
                hs2[i] = og * tanhf(c);
            }
        }
        __syncthreads();
    }

    if (is_tgt) {
        for (int i = tid; i < H; i += G4) g_tgt_emb[i] = hs2[i * BSENT];
    } else {
        for (int i = tid; i < H * BSENT; i += G4) {
            int u = i >> 4, b = i & 15;
            if (b < nb) g_sent_emb[(s0 + b) * H + u] = hs2[i];
        }
    }
}

// ---------------- kernel 3: sentence-level stacked LSTM chains -------------------
// 80 blocks: chain = bid/40 (0=prev, 1=post), layer = (bid/20)%2, part = bid%20.
// Each block owns 10 hidden units (40 gate rows), weights resident in smem.
// Cross-block handoff: per-part release flags, parallel polling.
__global__ __launch_bounds__(160, 1) void sent_lstm_kernel(
    const float* __restrict__ pWih, const float* __restrict__ pWhh,
    const float* __restrict__ pbih, const float* __restrict__ pbhh,
    const float* __restrict__ qWih, const float* __restrict__ qWhh,
    const float* __restrict__ qbih, const float* __restrict__ qbhh) {

    const int bid   = blockIdx.x;
    const int chain = bid / (2 * SPARTS);
    const int layer = (bid / SPARTS) & 1;
    const int part  = bid % SPARTS;

    const float* Wih = chain ? qWih : pWih;
    const float* Whh = chain ? qWhh : pWhh;
    const float* bih = chain ? qbih : pbih;
    const float* bhh = chain ? qbhh : pbhh;

    extern __shared__ float sm[];
    float* ws   = sm;                        // [40][SPITCH]: Wih row (200) ++ Whh row (200) ++ pad
    float* xh   = ws + SROWS * SPITCH;       // [400] = x(200) ++ h_prev(200)
    float* gbuf = xh + 400;                  // [40]
    float* bbuf = gbuf + SROWS;              // [40]
    float* cbuf = bbuf + SROWS;              // [10 + pad]

    const int tid = threadIdx.x;             // 160 threads = 5 warps

    // load this block's 40 gate rows (once; reused 1024 steps)
    for (int i = tid; i < SROWS * H; i += 160) {
        int rr = i / H, k = i % H;
        int r  = (rr / SUNITS) * H + part * SUNITS + (rr % SUNITS);  // gate*200 + unit
        ws[rr * SPITCH + k]     = Wih[layer * (G4 * H) + r * H + k];
        ws[rr * SPITCH + H + k] = Whh[layer * (G4 * H) + r * H + k];
    }
    if (tid < SROWS) {
        int r = (tid / SUNITS) * H + part * SUNITS + (tid % SUNITS);
        bbuf[tid] = bih[layer * G4 + r] + bhh[layer * G4 + r];
    }
    if (tid < SUNITS) cbuf[tid] = 0.f;
    __syncthreads();

    float* hist_own = (layer ? g_h1hist : g_h0hist) + chain * CH_T * H;
    const float* hist_in = g_h0hist + chain * CH_T * H;

    const int r = tid >> 2;          // row in 0..39
    const int s = tid & 3;           // k-segment 0..3 (100 floats each)
    const ulonglong2* wr2 = (const ulonglong2*)(ws + r * SPITCH + s * 100);
    const ulonglong2* xr2 = (const ulonglong2*)(xh + s * 100);

    for (int t = 0; t < CH_T; t++) {
        // wait for producers (parallel per-part polling, two warps for two deps)
        if (t > 0 && tid < SPARTS) {
            volatile int* f = &g_flag[chain][layer][tid];
            while (*f < t) { }
            __threadfence();
        }
        if (layer == 1 && tid >= 32 && tid < 32 + SPARTS) {
            volatile int* f = &g_flag[chain][0][tid - 32];
            while (*f < t + 1) { }
            __threadfence();
        }
        __syncthreads();

        // gather x_t into xh[0..199]
        if (layer == 0) {
            int sidx = chain ? (2 * MID - t) : t;               // post chain reversed
            const float* xp = (sidx == MID) ? g_tgt_emb : (g_sent_emb + sidx * H);
            for (int k = tid; k < H; k += 160) xh[k] = xp[k];
        } else {
            for (int k = tid; k < H; k += 160) xh[k] = __ldcg(&hist_in[t * H + k]);
        }
        // gather own-layer h_{t-1} into xh[200..399]
        if (t == 0) {
            for (int k = tid; k < H; k += 160) xh[H + k] = 0.f;
        } else {
            for (int k = tid; k < H; k += 160) xh[H + k] = __ldcg(&hist_own[(t - 1) * H + k]);
        }
        __syncthreads();

        // GEMV: 40 rows x 4 segments, packed fp32x2
        unsigned long long a0 = 0ull, a1 = 0ull;
        #pragma unroll
        for (int kk = 0; kk < 25; kk++) {
            ulonglong2 w = wr2[kk], x = xr2[kk];
            ffma2(a0, w.x, x.x);
            ffma2(a1, w.y, x.y);
        }
        float2 u0 = unpack2(a0), u1 = unpack2(a1);
        float ps = (u0.x + u0.y) + (u1.x + u1.y);
        ps += __shfl_down_sync(0xffffffffu, ps, 1);
        ps += __shfl_down_sync(0xffffffffu, ps, 2);
        if (s == 0) gbuf[r] = ps + bbuf[r];
        __syncthreads();

        if (tid < SUNITS) {
            float ig = sigm(gbuf[tid]);
            float fg = sigm(gbuf[SUNITS + tid]);
            float gg = tanhf(gbuf[2 * SUNITS + tid]);
            float og = sigm(gbuf[3 * SUNITS + tid]);
            float c  = fg * cbuf[tid] + ig * gg;
            cbuf[tid] = c;
            hist_own[t * H + part * SUNITS + tid] = og * tanhf(c);
            __threadfence();
        }
        __syncthreads();
        if (tid == 0) *(volatile int*)&g_flag[chain][layer][part] = t + 1;
    }
}

// ---------------- kernel 4: final projection ------------------------------------
__global__ void fc_kernel(const float* __restrict__ fc_W, const float* __restrict__ fc_b,
                          float* __restrict__ out) {
    int j = threadIdx.x;
    if (j < H) {
        const float* ph = g_h1hist + 0 * CH_T * H + (CH_T - 1) * H;
        const float* qh = g_h1hist + 1 * CH_T * H + (CH_T - 1) * H;
        float acc = fc_b[j];
        const float* wr = fc_W + j * (2 * H);
        #pragma unroll 4
        for (int k = 0; k < H; k++) acc += ph[k] * wr[k];
        #pragma unroll 4
        for (int k = 0; k < H; k++) acc += qh[k] * wr[H + k];
        out[j] = acc;
    }
}

// ---------------- launcher ------------------------------------------------------
extern "C" void kernel_launch(void* const* d_in, const int* in_sizes, int n_in,
                              void* d_out, int out_size) {
    const float* sents    = (const float*)d_in[0];
    const float* ctx_Wih  = (const float*)d_in[1];
    const float* ctx_Whh  = (const float*)d_in[2];
    const float* ctx_bih  = (const float*)d_in[3];
    const float* ctx_bhh  = (const float*)d_in[4];
    const float* tgt_Wih  = (const float*)d_in[5];
    const float* tgt_Whh  = (const float*)d_in[6];
    const float* tgt_bih  = (const float*)d_in[7];
    const float* tgt_bhh  = (const float*)d_in[8];
    const float* prev_Wih = (const float*)d_in[9];
    const float* prev_Whh = (const float*)d_in[10];
    const float* prev_bih = (const float*)d_in[11];
    const float* prev_bhh = (const float*)d_in[12];
    const float* post_Wih = (const float*)d_in[13];
    const float* post_Whh = (const float*)d_in[14];
    const float* post_bih = (const float*)d_in[15];
    const float* post_bhh = (const float*)d_in[16];
    const float* fc_W     = (const float*)d_in[17];
    const float* fc_b     = (const float*)d_in[18];

    const size_t word_smem = (size_t)(3 * H * BSENT + BSENT * GTP) * sizeof(float);          // 89664
    const size_t sent_smem = (size_t)(SROWS * SPITCH + 400 + 2 * SROWS + 16) * sizeof(float); // ~68.5KB

    cudaFuncSetAttribute(word_lstm_kernel, cudaFuncAttributeMaxDynamicSharedMemorySize, (int)word_smem);
    cudaFuncSetAttribute(sent_lstm_kernel, cudaFuncAttributeMaxDynamicSharedMemorySize, (int)sent_smem);

    zero_cnt_kernel<<<1, 128>>>();
    prep_kernel<<<(4 * H * G4 + 255) / 256, 256>>>(ctx_Wih, ctx_Whh, tgt_Wih, tgt_Whh,
                                                   ctx_bih, ctx_bhh, tgt_bih, tgt_bhh);
    word_lstm_kernel<<<NCTX + 1, G4, word_smem>>>(sents);
    sent_lstm_kernel<<<2 * 2 * SPARTS, 160, sent_smem>>>(prev_Wih, prev_Whh, prev_bih, prev_bhh,
                                                         post_Wih, post_Whh, post_bih, post_bhh);
    fc_kernel<<<1, 256>>>(fc_W, fc_b, (float*)d_out);
}

// round 5
// speedup vs baseline: 1.3026x; 1.3026x over previous
#include <cuda_runtime.h>
#include <math.h>
#include <stdint.h>

// Problem constants
#define H     200
#define G4    800          // 4*H
#define W     48
#define S     2047
#define MID   1023
#define BSENT 16           // sentences per block in word LSTM
#define NCTX  128          // ceil(2047/16)
#define CH_T  1024         // steps per sentence-level chain (MID+1)

// sentence-level partitioning (cluster of 8 blocks per (chain, layer))
#define SPARTS 8           // partition blocks per (chain, layer) == cluster size
#define SROWS  100         // gate rows per partition block (800/8)
#define SUNITS 25          // hidden units per partition block (200/8)
#define PITCH  424         // floats per weight row; rows tile banks conflict-free
#define HH_OFF 204         // offset of Whh half within a row

// ---------------- device scratch (no cudaMalloc allowed) ----------------
__device__ float g_WT[4][H * G4];          // [ctx_ih, ctx_hh, tgt_ih, tgt_hh] transposed [k][j]
__device__ float g_bias[2][G4];            // combined bih+bhh for ctx, tgt
__device__ float g_sent_emb[S * H];        // ctx embeddings
__device__ float g_tgt_emb[H];             // target-sentence embedding
__device__ float g_h0hist[2 * CH_T * H];   // [chain][t][H] layer-0 hidden history
__device__ float g_h1hist[2 * CH_T * H];   // [chain][t][H] layer-1 (only last step used)
__device__ int   g_flag[2][SPARTS][32];    // one 128B line per flag -> no L2 slice hotspot

__device__ __forceinline__ float sigm(float x) { return 1.f / (1.f + expf(-x)); }

__device__ __forceinline__ uint32_t smem_u32(const void* p) {
    uint32_t a;
    asm("{ .reg .u64 t; cvta.to.shared.u64 t, %1; cvt.u32.u64 %0, t; }" : "=r"(a) : "l"(p));
    return a;
}
__device__ __forceinline__ uint32_t ctarank() {
    uint32_t r; asm("mov.u32 %0, %%cluster_ctarank;" : "=r"(r)); return r;
}
__device__ __forceinline__ void mbar_init(uint32_t a, uint32_t cnt) {
    asm volatile("mbarrier.init.shared.b64 [%0], %1;" :: "r"(a), "r"(cnt) : "memory");
}
// parity wait with cluster-scope acquire (orders peers' DSMEM stores before our reads)
__device__ __forceinline__ void mbar_wait(uint32_t a, uint32_t par) {
    uint32_t done;
    asm volatile("{\n\t.reg .pred p;\n\t"
                 "mbarrier.try_wait.parity.acquire.cluster.shared::cta.b64 p, [%1], %2;\n\t"
                 "selp.b32 %0, 1, 0, p;\n\t}" : "=r"(done) : "r"(a), "r"(par) : "memory");
    while (!done) {
        asm volatile("{\n\t.reg .pred p;\n\t"
                     "mbarrier.try_wait.parity.acquire.cluster.shared::cta.b64 p, [%1], %2, 0x989680;\n\t"
                     "selp.b32 %0, 1, 0, p;\n\t}" : "=r"(done) : "r"(a), "r"(par) : "memory");
    }
}
// push one float into rank's smem and arrive (release) on rank's mbarrier.
// arrive is by the SAME thread that stored -> release covers the store.
__device__ __forceinline__ void dsmem_store_arrive(uint32_t laddr, float v, uint32_t lmbar, uint32_t rank) {
    asm volatile("{\n\t.reg .b32 ra, rb;\n\t"
                 "mapa.shared::cluster.u32 ra, %0, %2;\n\t"
                 "st.shared::cluster.f32 [ra], %1;\n\t"
                 "mapa.shared::cluster.u32 rb, %3, %2;\n\t"
                 "mbarrier.arrive.release.cluster.shared::cluster.b64 _, [rb];\n\t}"
                 :: "r"(laddr), "f"(v), "r"(rank), "r"(lmbar) : "memory");
}
__device__ __forceinline__ void cluster_sync_() {
    asm volatile("barrier.cluster.arrive.aligned;" ::: "memory");
    asm volatile("barrier.cluster.wait.aligned;" ::: "memory");
}

// ---------------- kernel 0: zero the sync flags (every replay) ----------------
__global__ void zero_cnt_kernel() {
    int i = blockIdx.x * blockDim.x + threadIdx.x;
    if (i < 2 * SPARTS * 32) ((int*)g_flag)[i] = 0;
}

// ---------------- kernel 1: transpose word-level weights + combine biases -------
__global__ void prep_kernel(const float* ci, const float* ch,
                            const float* ti, const float* th,
                            const float* cbi, const float* cbh,
                            const float* tbi, const float* tbh) {
    int idx = blockIdx.x * blockDim.x + threadIdx.x;
    if (idx < 4 * H * G4) {
        int m = idx / (H * G4);
        int r = idx % (H * G4);
        int k = r / G4;
        int j = r % G4;
        const float* src = (m == 0) ? ci : (m == 1) ? ch : (m == 2) ? ti : th;
        g_WT[m][r] = src[j * H + k];
    }
    if (idx < 2 * G4) {
        int m = idx / G4, j = idx % G4;
        g_bias[m][j] = m ? (tbi[j] + tbh[j]) : (cbi[j] + cbh[j]);
    }
}

// ---------------- kernel 2: word-level LSTMs (ctx batched + tgt) -----------------
// EXACT round-2 version (scalar float4 FMA) — the faster measured baseline.
__global__ __launch_bounds__(G4, 1) void word_lstm_kernel(const float* __restrict__ sents) {
    extern __shared__ float sm[];
    float* xs = sm;                      // [16][200]
    float* hs = xs + BSENT * H;          // [16][200]
    float* cs = hs + BSENT * H;          // [16][200]
    float* gt = cs + BSENT * H;          // [16][800]

    const int  bx     = blockIdx.x;
    const bool is_tgt = (bx == NCTX);
    const int  s0     = is_tgt ? MID : bx * BSENT;
    const int  nb     = is_tgt ? 1 : ((S - s0) < BSENT ? (S - s0) : BSENT);

    const float* __restrict__ WTih = is_tgt ? g_WT[2] : g_WT[0];
    const float* __restrict__ WThh = is_tgt ? g_WT[3] : g_WT[1];
    const float* __restrict__ bias = is_tgt ? g_bias[1] : g_bias[0];

    const int tid = threadIdx.x;          // == gate row j
    for (int i = tid; i < BSENT * H; i += G4) { xs[i] = 0.f; hs[i] = 0.f; cs[i] = 0.f; }
    const float bj = bias[tid];
    const float* wi = WTih + tid;
    const float* wh = WThh + tid;
    __syncthreads();

    for (int t = 0; t < W; t++) {
        for (int i = tid; i < nb * H; i += G4) {
            int b = i / H, k = i % H;
            xs[b * H + k] = sents[(long)(s0 + b) * (W * H) + t * H + k];
        }
        __syncthreads();

        float acc[BSENT];
        #pragma unroll
        for (int b = 0; b < BSENT; b++) acc[b] = bj;

        #pragma unroll 2
        for (int k = 0; k < H; k += 4) {
            float w0 = wi[(k + 0) * G4], w1 = wi[(k + 1) * G4];
            float w2 = wi[(k + 2) * G4], w3 = wi[(k + 3) * G4];
            #pragma unroll
            for (int b = 0; b < BSENT; b++) {
                float4 xv = *(const float4*)&xs[b * H + k];
                acc[b] += w0 * xv.x + w1 * xv.y + w2 * xv.z + w3 * xv.w;
            }
        }
        #pragma unroll 2
        for (int k = 0; k < H; k += 4) {
            float w0 = wh[(k + 0) * G4], w1 = wh[(k + 1) * G4];
            float w2 = wh[(k + 2) * G4], w3 = wh[(k + 3) * G4];
            #pragma unroll
            for (int b = 0; b < BSENT; b++) {
                float4 hv = *(const float4*)&hs[b * H + k];
                acc[b] += w0 * hv.x + w1 * hv.y + w2 * hv.z + w3 * hv.w;
            }
        }
        #pragma unroll
        for (int b = 0; b < BSENT; b++) gt[b * G4 + tid] = acc[b];
        __syncthreads();

        for (int i = tid; i < BSENT * H; i += G4) {
            int b = i / H, u = i % H;
            if (b < nb) {
                float ig = sigm(gt[b * G4 + u]);
                float fg = sigm(gt[b * G4 + H + u]);
                float gg = tanhf(gt[b * G4 + 2 * H + u]);
                float og = sigm(gt[b * G4 + 3 * H + u]);
                float c  = fg * cs[b * H + u] + ig * gg;
                cs[b * H + u] = c;
                hs[b * H + u] = og * tanhf(c);
            }
        }
        __syncthreads();
    }

    if (is_tgt) {
        for (int i = tid; i < H; i += G4) g_tgt_emb[i] = hs[i];
    } else {
        for (int i = tid; i < nb * H; i += G4) {
            int b = i / H, u = i % H;
            g_sent_emb[(s0 + b) * H + u] = hs[b * H + u];
        }
    }
}

// ---------------- kernel 3: sentence-level stacked LSTM chains (CGA/DSMEM) -------
// 32 blocks, clusters of 8. group = bid/8: 0=(c0,l0) 1=(c0,l1) 2=(c1,l0) 3=(c1,l1).
// Within a cluster: each CTA owns 25 h-units (100 gate rows), weights smem-resident.
// h_{t-1} broadcast via DSMEM pushes + mbarrier (double-buffered).
// layer0 -> layer1 via L2 hist + padded per-part flags.
// dynamic smem (floats): [0:4) mbar(2xu64) | [4:204) xbuf | [204:604) hbuf[2][200]
//                        | [604:704) gbuf | [704:804) bbuf | [804:836) hout | [836:...) ws
__global__ __launch_bounds__(256, 1) __cluster_dims__(SPARTS, 1, 1)
void sent_lstm_kernel(
    const float* __restrict__ pWih, const float* __restrict__ pWhh,
    const float* __restrict__ pbih, const float* __restrict__ pbhh,
    const float* __restrict__ qWih, const float* __restrict__ qWhh,
    const float* __restrict__ qbih, const float* __restrict__ qbhh) {

    extern __shared__ float sm[];
    float* xbuf = sm + 4;
    float* hbuf = sm + 204;          // [2][200]
    float* gbuf = sm + 604;          // [100]
    float* bbuf = sm + 704;          // [100]
    float* hout = sm + 804;          // [25]
    float* ws   = sm + 836;          // [100][PITCH]

    const int tid   = threadIdx.x;   // 256 threads
    const int group = blockIdx.x >> 3;
    const int chain = group >> 1;
    const int layer = group & 1;
    const uint32_t part = ctarank();

    const float* Wih = chain ? qWih : pWih;
    const float* Whh = chain ? qWhh : pWhh;
    const float* bih = chain ? qbih : pbih;
    const float* bhh = chain ? qbhh : pbhh;

    const uint32_t smbase = smem_u32(sm);
    const uint32_t mbar0  = smbase;            // 8 bytes each, two barriers
    const uint32_t hbuf_a = smbase + 204 * 4;

    // init
    if (tid == 0) { mbar_init(mbar0, SPARTS * SUNITS); mbar_init(mbar0 + 8, SPARTS * SUNITS); }
    for (int i = tid; i < 400; i += 256) hbuf[i] = 0.f;
    for (int i = tid; i < SROWS * 2 * H; i += 256) {
        int rr = i / (2 * H), kk = i % (2 * H);
        int r  = (rr / SUNITS) * H + (int)part * SUNITS + (rr % SUNITS);  // gate*200 + unit
        if (kk < H) ws[rr * PITCH + kk]              = Wih[layer * (G4 * H) + r * H + kk];
        else        ws[rr * PITCH + HH_OFF + kk - H] = Whh[layer * (G4 * H) + r * H + kk - H];
    }
    if (tid < SROWS) {
        int r = (tid / SUNITS) * H + (int)part * SUNITS + (tid % SUNITS);
        bbuf[tid] = bih[layer * G4 + r] + bhh[layer * G4 + r];
    }
    __syncthreads();
    cluster_sync_();                 // mbarriers + zeroed hbuf visible cluster-wide

    float cstate = 0.f;              // cell state lives in registers of tid<25
    int ph0 = 0, ph1 = 0;
    const float* hist0  = g_h0hist + chain * CH_T * H;
    float*       hist0w = g_h0hist + chain * CH_T * H;

    const int r = tid >> 1, s = tid & 1;
    const float4* wv = (const float4*)(ws + r * PITCH + s * HH_OFF);

    for (int t = 0; t < CH_T; t++) {
        // layer-1: wait for layer-0 step t (padded flags, parallel pollers)
        if (layer == 1) {
            if (tid < SPARTS) {
                volatile int* f = &g_flag[chain][tid][0];
                while (*f < t + 1) { }
                __threadfence();
            }
            __syncthreads();
        }
        // issue x loads before the h-barrier wait (hide L2 latency)
        float rx = 0.f;
        if (tid < H) {
            if (layer == 0) {
                int sidx = chain ? (2 * MID - t) : t;
                rx = (sidx == MID) ? g_tgt_emb[tid] : g_sent_emb[sidx * H + tid];
            } else {
                rx = __ldcg(&hist0[t * H + tid]);
            }
        }
        // wait for h(t-1) from all cluster peers
        if (t > 0) {
            int b = (t - 1) & 1;
            if (b == 0) { mbar_wait(mbar0, ph0); ph0 ^= 1; }
            else        { mbar_wait(mbar0 + 8, ph1); ph1 ^= 1; }
        }
        if (tid < H) xbuf[tid] = rx;
        __syncthreads();

        // GEMV: 2 threads per row; s=0 -> Wih.x, s=1 -> Whh.h
        float ps = 0.f;
        if (tid < 2 * SROWS) {
            const float4* xv = (const float4*)(s ? (hbuf + ((t + 1) & 1) * H) : xbuf);
            float a0 = 0.f, a1 = 0.f, a2 = 0.f, a3 = 0.f;
            #pragma unroll 10
            for (int k = 0; k < 50; k++) {
                float4 w = wv[k], x = xv[k];
                a0 += w.x * x.x; a1 += w.y * x.y;
                a2 += w.z * x.z; a3 += w.w * x.w;
            }
            ps = (a0 + a1) + (a2 + a3);
        }
        ps += __shfl_down_sync(0xffffffffu, ps, 1);
        if (tid < 2 * SROWS && s == 0) gbuf[r] = ps + bbuf[r];
        __syncthreads();

        // cell update (25 units)
        if (tid < SUNITS) {
            float ig = sigm(gbuf[tid]);
            float fg = sigm(gbuf[SUNITS + tid]);
            float gg = tanhf(gbuf[2 * SUNITS + tid]);
            float og = sigm(gbuf[3 * SUNITS + tid]);
            float c  = fg * cstate + ig * gg;
            cstate = c;
            float h = og * tanhf(c);
            hout[tid] = h;
            if (layer == 0) {
                hist0w[t * H + (int)part * SUNITS + tid] = h;
                __threadfence();
            } else if (t == CH_T - 1) {
                g_h1hist[chain * CH_T * H + t * H + (int)part * SUNITS + tid] = h;
            }
        }
        __syncthreads();

        // broadcast h slice to all 8 cluster peers; per-lane store+arrive (release)
        {
            int lid = tid & 31, w = tid >> 5;   // 8 warps -> 8 destination ranks
            if (lid < SUNITS) {
                uint32_t la = hbuf_a + ((t & 1) * H + (int)part * SUNITS + lid) * 4;
                dsmem_store_arrive(la, hout[lid], mbar0 + (t & 1) * 8, (uint32_t)w);
            }
        }
        if (layer == 0 && tid == 0)
            *(volatile int*)&g_flag[chain][part][0] = t + 1;
    }

    // single cluster barrier: every CTA's final store+arrive precedes its arrive
    // (release), so after the wait all remote traffic into our smem is complete.
    cluster_sync_();
}

// ---------------- kernel 4: final projection ------------------------------------
__global__ void fc_kernel(const float* __restrict__ fc_W, const float* __restrict__ fc_b,
                          float* __restrict__ out) {
    int j = threadIdx.x;
    if (j < H) {
        const float* ph = g_h1hist + 0 * CH_T * H + (CH_T - 1) * H;
        const float* qh = g_h1hist + 1 * CH_T * H + (CH_T - 1) * H;
        float acc = fc_b[j];
        const float* wr = fc_W + j * (2 * H);
        #pragma unroll 4
        for (int k = 0; k < H; k++) acc += ph[k] * wr[k];
        #pragma unroll 4
        for (int k = 0; k < H; k++) acc += qh[k] * wr[H + k];
        out[j] = acc;
    }
}

// ---------------- launcher ------------------------------------------------------
extern "C" void kernel_launch(void* const* d_in, const int* in_sizes, int n_in,
                              void* d_out, int out_size) {
    const float* sents    = (const float*)d_in[0];
    const float* ctx_Wih  = (const float*)d_in[1];
    const float* ctx_Whh  = (const float*)d_in[2];
    const float* ctx_bih  = (const float*)d_in[3];
    const float* ctx_bhh  = (const float*)d_in[4];
    const float* tgt_Wih  = (const float*)d_in[5];
    const float* tgt_Whh  = (const float*)d_in[6];
    const float* tgt_bih  = (const float*)d_in[7];
    const float* tgt_bhh  = (const float*)d_in[8];
    const float* prev_Wih = (const float*)d_in[9];
    const float* prev_Whh = (const float*)d_in[10];
    const float* prev_bih = (const float*)d_in[11];
    const float* prev_bhh = (const float*)d_in[12];
    const float* post_Wih = (const float*)d_in[13];
    const float* post_Whh = (const float*)d_in[14];
    const float* post_bih = (const float*)d_in[15];
    const float* post_bhh = (const float*)d_in[16];
    const float* fc_W     = (const float*)d_in[17];
    const float* fc_b     = (const float*)d_in[18];

    const size_t word_smem = (size_t)(3 * BSENT * H + BSENT * G4) * sizeof(float);  // 89600
    const size_t sent_smem = (size_t)(836 + SROWS * PITCH) * sizeof(float);         // 172944

    cudaFuncSetAttribute(word_lstm_kernel, cudaFuncAttributeMaxDynamicSharedMemorySize, (int)word_smem);
    cudaFuncSetAttribute(sent_lstm_kernel, cudaFuncAttributeMaxDynamicSharedMemorySize, (int)sent_smem);

    zero_cnt_kernel<<<1, 512>>>();
    prep_kernel<<<(4 * H * G4 + 255) / 256, 256>>>(ctx_Wih, ctx_Whh, tgt_Wih, tgt_Whh,
                                                   ctx_bih, ctx_bhh, tgt_bih, tgt_bhh);
    word_lstm_kernel<<<NCTX + 1, G4, word_smem>>>(sents);
    sent_lstm_kernel<<<4 * SPARTS, 256, sent_smem>>>(prev_Wih, prev_Whh, prev_bih, prev_bhh,
                                                     post_Wih, post_Whh, post_bih, post_bhh);
    fc_kernel<<<1, 256>>>(fc_W, fc_b, (float*)d_out);
}

// round 6
// speedup vs baseline: 1.3683x; 1.0505x over previous
#include <cuda_runtime.h>
#include <math.h>
#include <stdint.h>

// Problem constants
#define H     200
#define G4    800          // 4*H
#define W     48
#define S     2047
#define MID   1023
#define BSENT 16           // sentences per block in word LSTM
#define NCTX  128          // ceil(2047/16)
#define CH_T  1024         // steps per sentence-level chain (MID+1)

// sentence-level partitioning: one 16-CTA cluster per chain (8 CTAs per layer)
#define SPARTS 8           // partition CTAs per layer
#define CLSZ   16          // cluster size (nonportable)
#define SROWS  100         // gate rows per CTA (800/8)
#define SUNITS 25          // hidden units per CTA (200/8)
#define PITCH  424         // floats per weight row (bank-conflict-free tiling)
#define HH_OFF 204         // offset of Whh half within a row

// smem float offsets for sent kernel
#define OFF_XBUF 16        // [2][200] x double buffer
#define OFF_HBUF 416       // [2][200] own-layer h double buffer
#define OFF_GBUF 816       // [100]
#define OFF_BBUF 916       // [100]
#define OFF_HOUT 1016      // [32]
#define OFF_WS   1048      // [100][PITCH]
#define SENT_SMEM_FLOATS (OFF_WS + SROWS * PITCH)

// ---------------- device scratch (no cudaMalloc allowed) ----------------
__device__ float g_WT[4][H * G4];          // [ctx_ih, ctx_hh, tgt_ih, tgt_hh] transposed [k][j]
__device__ float g_bias[2][G4];            // combined bih+bhh for ctx, tgt
__device__ float g_sent_emb[S * H];        // ctx embeddings
__device__ float g_tgt_emb[H];             // target-sentence embedding
__device__ float g_final[2 * H];           // [chain][H] top-layer final hidden

__device__ __forceinline__ float sigm(float x) { return 1.f / (1.f + expf(-x)); }

__device__ __forceinline__ uint32_t smem_u32(const void* p) {
    uint32_t a;
    asm("{ .reg .u64 t; cvta.to.shared.u64 t, %1; cvt.u32.u64 %0, t; }" : "=r"(a) : "l"(p));
    return a;
}
__device__ __forceinline__ uint32_t ctarank() {
    uint32_t r; asm("mov.u32 %0, %%cluster_ctarank;" : "=r"(r)); return r;
}
__device__ __forceinline__ void mbar_init(uint32_t a, uint32_t cnt) {
    asm volatile("mbarrier.init.shared.b64 [%0], %1;" :: "r"(a), "r"(cnt) : "memory");
}
// parity wait with cluster-scope acquire (orders peers' DSMEM stores before our reads)
__device__ __forceinline__ void mbar_wait(uint32_t a, uint32_t par) {
    uint32_t done;
    asm volatile("{\n\t.reg .pred p;\n\t"
                 "mbarrier.try_wait.parity.acquire.cluster.shared::cta.b64 p, [%1], %2;\n\t"
                 "selp.b32 %0, 1, 0, p;\n\t}" : "=r"(done) : "r"(a), "r"(par) : "memory");
    while (!done) {
        asm volatile("{\n\t.reg .pred p;\n\t"
                     "mbarrier.try_wait.parity.acquire.cluster.shared::cta.b64 p, [%1], %2, 0x989680;\n\t"
                     "selp.b32 %0, 1, 0, p;\n\t}" : "=r"(done) : "r"(a), "r"(par) : "memory");
    }
}
// push one float into rank's smem and arrive (release) on rank's mbarrier.
// arrive is by the SAME thread that stored -> release covers the store.
__device__ __forceinline__ void dsmem_store_arrive(uint32_t laddr, float v, uint32_t lmbar, uint32_t rank) {
    asm volatile("{\n\t.reg .b32 ra, rb;\n\t"
                 "mapa.shared::cluster.u32 ra, %0, %2;\n\t"
                 "st.shared::cluster.f32 [ra], %1;\n\t"
                 "mapa.shared::cluster.u32 rb, %3, %2;\n\t"
                 "mbarrier.arrive.release.cluster.shared::cluster.b64 _, [rb];\n\t}"
                 :: "r"(laddr), "f"(v), "r"(rank), "r"(lmbar) : "memory");
}
// remote arrive only (credit return)
__device__ __forceinline__ void dsmem_arrive(uint32_t lmbar, uint32_t rank) {
    asm volatile("{\n\t.reg .b32 rb;\n\t"
                 "mapa.shared::cluster.u32 rb, %0, %1;\n\t"
                 "mbarrier.arrive.release.cluster.shared::cluster.b64 _, [rb];\n\t}"
                 :: "r"(lmbar), "r"(rank) : "memory");
}
__device__ __forceinline__ void cluster_sync_() {
    asm volatile("barrier.cluster.arrive.aligned;" ::: "memory");
    asm volatile("barrier.cluster.wait.aligned;" ::: "memory");
}

// ---------------- kernel 1: transpose word-level weights + combine biases -------
__global__ void prep_kernel(const float* ci, const float* ch,
                            const float* ti, const float* th,
                            const float* cbi, const float* cbh,
                            const float* tbi, const float* tbh) {
    int idx = blockIdx.x * blockDim.x + threadIdx.x;
    if (idx < 4 * H * G4) {
        int m = idx / (H * G4);
        int r = idx % (H * G4);
        int k = r / G4;
        int j = r % G4;
        const float* src = (m == 0) ? ci : (m == 1) ? ch : (m == 2) ? ti : th;
        g_WT[m][r] = src[j * H + k];
    }
    if (idx < 2 * G4) {
        int m = idx / G4, j = idx % G4;
        g_bias[m][j] = m ? (tbi[j] + tbh[j]) : (cbi[j] + cbh[j]);
    }
}

// ---------------- kernel 2: word-level LSTMs (unchanged measured baseline) -------
__global__ __launch_bounds__(G4, 1) void word_lstm_kernel(const float* __restrict__ sents) {
    extern __shared__ float sm[];
    float* xs = sm;                      // [16][200]
    float* hs = xs + BSENT * H;          // [16][200]
    float* cs = hs + BSENT * H;          // [16][200]
    float* gt = cs + BSENT * H;          // [16][800]

    const int  bx     = blockIdx.x;
    const bool is_tgt = (bx == NCTX);
    const int  s0     = is_tgt ? MID : bx * BSENT;
    const int  nb     = is_tgt ? 1 : ((S - s0) < BSENT ? (S - s0) : BSENT);

    const float* __restrict__ WTih = is_tgt ? g_WT[2] : g_WT[0];
    const float* __restrict__ WThh = is_tgt ? g_WT[3] : g_WT[1];
    const float* __restrict__ bias = is_tgt ? g_bias[1] : g_bias[0];

    const int tid = threadIdx.x;          // == gate row j
    for (int i = tid; i < BSENT * H; i += G4) { xs[i] = 0.f; hs[i] = 0.f; cs[i] = 0.f; }
    const float bj = bias[tid];
    const float* wi = WTih + tid;
    const float* wh = WThh + tid;
    __syncthreads();

    for (int t = 0; t < W; t++) {
        for (int i = tid; i < nb * H; i += G4) {
            int b = i / H, k = i % H;
            xs[b * H + k] = sents[(long)(s0 + b) * (W * H) + t * H + k];
        }
        __syncthreads();

        float acc[BSENT];
        #pragma unroll
        for (int b = 0; b < BSENT; b++) acc[b] = bj;

        #pragma unroll 2
        for (int k = 0; k < H; k += 4) {
            float w0 = wi[(k + 0) * G4], w1 = wi[(k + 1) * G4];
            float w2 = wi[(k + 2) * G4], w3 = wi[(k + 3) * G4];
            #pragma unroll
            for (int b = 0; b < BSENT; b++) {
                float4 xv = *(const float4*)&xs[b * H + k];
                acc[b] += w0 * xv.x + w1 * xv.y + w2 * xv.z + w3 * xv.w;
            }
        }
        #pragma unroll 2
        for (int k = 0; k < H; k += 4) {
            float w0 = wh[(k + 0) * G4], w1 = wh[(k + 1) * G4];
            float w2 = wh[(k + 2) * G4], w3 = wh[(k + 3) * G4];
            #pragma unroll
            for (int b = 0; b < BSENT; b++) {
                float4 hv = *(const float4*)&hs[b * H + k];
                acc[b] += w0 * hv.x + w1 * hv.y + w2 * hv.z + w3 * hv.w;
            }
        }
        #pragma unroll
        for (int b = 0; b < BSENT; b++) gt[b * G4 + tid] = acc[b];
        __syncthreads();

        for (int i = tid; i < BSENT * H; i += G4) {
            int b = i / H, u = i % H;
            if (b < nb) {
                float ig = sigm(gt[b * G4 + u]);
                float fg = sigm(gt[b * G4 + H + u]);
                float gg = tanhf(gt[b * G4 + 2 * H + u]);
                float og = sigm(gt[b * G4 + 3 * H + u]);
                float c  = fg * cs[b * H + u] + ig * gg;
                cs[b * H + u] = c;
                hs[b * H + u] = og * tanhf(c);
            }
        }
        __syncthreads();
    }

    if (is_tgt) {
        for (int i = tid; i < H; i += G4) g_tgt_emb[i] = hs[i];
    } else {
        for (int i = tid; i < nb * H; i += G4) {
            int b = i / H, u = i % H;
            g_sent_emb[(s0 + b) * H + u] = hs[b * H + u];
        }
    }
}

// ---------------- kernel 3: sentence-level chains, 16-CTA cluster, all-DSMEM -----
// grid 32 = 2 clusters x 16 CTAs. chain = blockIdx.x/16.
// rank 0..7 = layer 0 parts, rank 8..15 = layer 1 parts. Each CTA: 25 units.
// layer0 step t: x from gmem embeddings; pushes h0(t) -> l0 peers' hbuf AND l1 CTAs' xbuf.
// layer1 step t: x via xbar (from l0), h via hbar; returns credit to l0 (WAR backpressure).
// barriers (local smem): hbar[2]@0,8  xbar[2]@16,24  credit[2]@32,40 (bytes)
__global__ __launch_bounds__(256, 1)
void sent_lstm_kernel(
    const float* __restrict__ pWih, const float* __restrict__ pWhh,
    const float* __restrict__ pbih, const float* __restrict__ pbhh,
    const float* __restrict__ qWih, const float* __restrict__ qWhh,
    const float* __restrict__ qbih, const float* __restrict__ qbhh) {

    extern __shared__ float sm[];
    float* xbuf = sm + OFF_XBUF;     // [2][200]
    float* hbuf = sm + OFF_HBUF;     // [2][200]
    float* gbuf = sm + OFF_GBUF;     // [100]
    float* bbuf = sm + OFF_BBUF;     // [100]
    float* hout = sm + OFF_HOUT;     // [32]
    float* ws   = sm + OFF_WS;       // [100][PITCH]

    const int tid   = threadIdx.x;   // 256 threads
    const int chain = blockIdx.x >> 4;
    const uint32_t rank = ctarank();
    const int layer = (int)(rank >> 3);
    const int part  = (int)(rank & 7);

    const float* Wih = chain ? qWih : pWih;
    const float* Whh = chain ? qWhh : pWhh;
    const float* bih = chain ? qbih : pbih;
    const float* bhh = chain ? qbhh : pbhh;

    const uint32_t smbase = smem_u32(sm);
    const uint32_t HBAR   = smbase;        // +b*8
    const uint32_t XBAR   = smbase + 16;   // +b*8
    const uint32_t CBAR   = smbase + 32;   // +b*8

    if (tid == 0) {
        mbar_init(HBAR,     SPARTS * SUNITS);  mbar_init(HBAR + 8, SPARTS * SUNITS);
        mbar_init(XBAR,     SPARTS * SUNITS);  mbar_init(XBAR + 8, SPARTS * SUNITS);
        mbar_init(CBAR,     SPARTS);           mbar_init(CBAR + 8, SPARTS);
    }
    for (int i = tid; i < 2 * H; i += 256) hbuf[i] = 0.f;
    for (int i = tid; i < SROWS * 2 * H; i += 256) {
        int rr = i / (2 * H), kk = i % (2 * H);
        int r  = (rr / SUNITS) * H + part * SUNITS + (rr % SUNITS);  // gate*200 + unit
        if (kk < H) ws[rr * PITCH + kk]              = Wih[layer * (G4 * H) + r * H + kk];
        else        ws[rr * PITCH + HH_OFF + kk - H] = Whh[layer * (G4 * H) + r * H + kk - H];
    }
    if (tid < SROWS) {
        int r = (tid / SUNITS) * H + part * SUNITS + (tid % SUNITS);
        bbuf[tid] = bih[layer * G4 + r] + bhh[layer * G4 + r];
    }
    __syncthreads();
    cluster_sync_();                 // all mbarriers + zeroed hbuf visible cluster-wide

    float cstate = 0.f;              // cell state in registers of tid<25
    int ph_h0 = 0, ph_h1 = 0, ph_x0 = 0, ph_x1 = 0, ph_c0 = 0, ph_c1 = 0;

    const int r = tid >> 1, s = tid & 1;
    const float4* wv = (const float4*)(ws + r * PITCH + s * HH_OFF);

    for (int t = 0; t < CH_T; t++) {
        const int b = t & 1;
        if (layer == 0) {
            // WAR credit: layer1 consumed x(t-2) before we overwrite buffer b remotely
            if (t >= 2) {
                if (b == 0) { mbar_wait(CBAR, ph_c0); ph_c0 ^= 1; }
                else        { mbar_wait(CBAR + 8, ph_c1); ph_c1 ^= 1; }
            }
            if (tid < H) {
                int sidx = chain ? (2 * MID - t) : t;
                float v = (sidx == MID) ? g_tgt_emb[tid] : g_sent_emb[sidx * H + tid];
                xbuf[b * H + tid] = v;
            }
        } else {
            // x(t) pushed by layer0
            if (b == 0) { mbar_wait(XBAR, ph_x0); ph_x0 ^= 1; }
            else        { mbar_wait(XBAR + 8, ph_x1); ph_x1 ^= 1; }
        }
        // own-layer h(t-1)
        if (t > 0) {
            int hb = (t - 1) & 1;
            if (hb == 0) { mbar_wait(HBAR, ph_h0); ph_h0 ^= 1; }
            else         { mbar_wait(HBAR + 8, ph_h1); ph_h1 ^= 1; }
        }
        __syncthreads();

        // GEMV: 2 threads/row; s=0 -> Wih.x, s=1 -> Whh.h(t-1)
        float ps = 0.f;
        if (tid < 2 * SROWS) {
            const float4* xv = (const float4*)(s ? (hbuf + ((t + 1) & 1) * H) : (xbuf + b * H));
            float a0 = 0.f, a1 = 0.f, a2 = 0.f, a3 = 0.f;
            #pragma unroll 10
            for (int k = 0; k < 50; k++) {
                float4 w = wv[k], x = xv[k];
                a0 += w.x * x.x; a1 += w.y * x.y;
                a2 += w.z * x.z; a3 += w.w * x.w;
            }
            ps = (a0 + a1) + (a2 + a3);
        }
        ps += __shfl_down_sync(0xffffffffu, ps, 1);
        if (tid < 2 * SROWS && s == 0) gbuf[r] = ps + bbuf[r];
        __syncthreads();

        // xbuf[b] fully consumed -> return credit to all layer0 CTAs (ranks 0..7)
        if (layer == 1 && tid < SPARTS) dsmem_arrive(CBAR + b * 8, (uint32_t)tid);

        // cell update (25 units)
        if (tid < SUNITS) {
            float ig = sigm(gbuf[tid]);
            float fg = sigm(gbuf[SUNITS + tid]);
            float gg = tanhf(gbuf[2 * SUNITS + tid]);
            float og = sigm(gbuf[3 * SUNITS + tid]);
            float c  = fg * cstate + ig * gg;
            cstate = c;
            float h = og * tanhf(c);
            hout[tid] = h;
            if (layer == 1 && t == CH_T - 1)
                g_final[chain * H + part * SUNITS + tid] = h;
        }
        __syncthreads();

        // DSMEM pushes: warp w serves dest rank(s); lanes 0..24 carry the 25 values
        {
            int lid = tid & 31, w = tid >> 5;   // 8 warps
            if (lid < SUNITS) {
                float v = hout[lid];
                uint32_t slot = (uint32_t)(b * H + part * SUNITS + lid) * 4u;
                if (layer == 0) {
                    // h0 -> layer0 peers' hbuf (next step) and layer1 CTAs' xbuf (their x(t))
                    dsmem_store_arrive(smbase + OFF_HBUF * 4 + slot, v, HBAR + b * 8, (uint32_t)w);
                    dsmem_store_arrive(smbase + OFF_XBUF * 4 + slot, v, XBAR + b * 8, (uint32_t)(w + 8));
                } else {
                    dsmem_store_arrive(smbase + OFF_HBUF * 4 + slot, v, HBAR + b * 8, (uint32_t)(w + 8));
                }
            }
        }
    }

    // keep every CTA's smem alive until all cluster traffic has landed
    cluster_sync_();
}

// ---------------- kernel 4: final projection ------------------------------------
__global__ void fc_kernel(const float* __restrict__ fc_W, const float* __restrict__ fc_b,
                          float* __restrict__ out) {
    int j = threadIdx.x;
    if (j < H) {
        const float* ph = g_final;
        const float* qh = g_final + H;
        float acc = fc_b[j];
        const float* wr = fc_W + j * (2 * H);
        #pragma unroll 4
        for (int k = 0; k < H; k++) acc += ph[k] * wr[k];
        #pragma unroll 4
        for (int k = 0; k < H; k++) acc += qh[k] * wr[H + k];
        out[j] = acc;
    }
}

// ---------------- launcher ------------------------------------------------------
extern "C" void kernel_launch(void* const* d_in, const int* in_sizes, int n_in,
                              void* d_out, int out_size) {
    const float* sents    = (const float*)d_in[0];
    const float* ctx_Wih  = (const float*)d_in[1];
    const float* ctx_Whh  = (const float*)d_in[2];
    const float* ctx_bih  = (const float*)d_in[3];
    const float* ctx_bhh  = (const float*)d_in[4];
    const float* tgt_Wih  = (const float*)d_in[5];
    const float* tgt_Whh  = (const float*)d_in[6];
    const float* tgt_bih  = (const float*)d_in[7];
    const float* tgt_bhh  = (const float*)d_in[8];
    const float* prev_Wih = (const float*)d_in[9];
    const float* prev_Whh = (const float*)d_in[10];
    const float* prev_bih = (const float*)d_in[11];
    const float* prev_bhh = (const float*)d_in[12];
    const float* post_Wih = (const float*)d_in[13];
    const float* post_Whh = (const float*)d_in[14];
    const float* post_bih = (const float*)d_in[15];
    const float* post_bhh = (const float*)d_in[16];
    const float* fc_W     = (const float*)d_in[17];
    const float* fc_b     = (const float*)d_in[18];

    const size_t word_smem = (size_t)(3 * BSENT * H + BSENT * G4) * sizeof(float);  // 89600
    const size_t sent_smem = (size_t)SENT_SMEM_FLOATS * sizeof(float);              // 173792

    cudaFuncSetAttribute(word_lstm_kernel, cudaFuncAttributeMaxDynamicSharedMemorySize, (int)word_smem);
    cudaFuncSetAttribute(sent_lstm_kernel, cudaFuncAttributeMaxDynamicSharedMemorySize, (int)sent_smem);
    cudaFuncSetAttribute(sent_lstm_kernel, cudaFuncAttributeNonPortableClusterSizeAllowed, 1);

    prep_kernel<<<(4 * H * G4 + 255) / 256, 256>>>(ctx_Wih, ctx_Whh, tgt_Wih, tgt_Whh,
                                                   ctx_bih, ctx_bhh, tgt_bih, tgt_bhh);
    word_lstm_kernel<<<NCTX + 1, G4, word_smem>>>(sents);

    {
        cudaLaunchConfig_t cfg = {};
        cfg.gridDim  = dim3(2 * CLSZ, 1, 1);
        cfg.blockDim = dim3(256, 1, 1);
        cfg.dynamicSmemBytes = sent_smem;
        cfg.stream = 0;
        cudaLaunchAttribute attr[1];
        attr[0].id = cudaLaunchAttributeClusterDimension;
        attr[0].val.clusterDim.x = CLSZ;
        attr[0].val.clusterDim.y = 1;
        attr[0].val.clusterDim.z = 1;
        cfg.attrs = attr;
        cfg.numAttrs = 1;
        cudaLaunchKernelEx(&cfg, sent_lstm_kernel,
                           prev_Wih, prev_Whh, prev_bih, prev_bhh,
                           post_Wih, post_Whh, post_bih, post_bhh);
    }

    fc_kernel<<<1, 256>>>(fc_W, fc_b, (float*)d_out);
}